// round 1
// baseline (speedup 1.0000x reference)
#include <cuda_runtime.h>

#define IMG_W 512
#define IMG_H 512
#define PLANES 64
#define PLANE_STRIDE (IMG_H * IMG_W)
#define NPIX (PLANES * PLANE_STRIDE)
#define EPS 1e-10f

// scratch accumulator (no device allocation allowed)
__device__ double g_ngf_acc;

__global__ void ngf_zero_kernel() { g_ngf_acc = 0.0; }

__global__ __launch_bounds__(256) void ngf_main_kernel(
    const float* __restrict__ I0, const float* __restrict__ I1)
{
    const int idx = blockIdx.x * 256 + threadIdx.x;   // one float4-group per thread
    const int c4  = idx & 127;          // 128 groups of 4 cols
    const int r   = (idx >> 7) & 511;   // row
    const int p   = idx >> 16;          // plane (batch*channel)
    const int c   = c4 << 2;

    const float* __restrict__ b0 = I0 + p * PLANE_STRIDE;
    const float* __restrict__ b1 = I1 + p * PLANE_STRIDE;

    const int ra = (r > 0) ? r - 1 : 0;             // row for "minus" side of gx
    const int rb = (r < IMG_H - 1) ? r + 1 : IMG_H - 1; // row for "plus" side of gx
    const int rowOff = r * IMG_W + c;

    // image 0 loads
    const float4 cen0 = *reinterpret_cast<const float4*>(b0 + rowOff);
    const float4 up0  = *reinterpret_cast<const float4*>(b0 + ra * IMG_W + c);
    const float4 dn0  = *reinterpret_cast<const float4*>(b0 + rb * IMG_W + c);
    // image 1 loads
    const float4 cen1 = *reinterpret_cast<const float4*>(b1 + rowOff);
    const float4 up1  = *reinterpret_cast<const float4*>(b1 + ra * IMG_W + c);
    const float4 dn1  = *reinterpret_cast<const float4*>(b1 + rb * IMG_W + c);

    // horizontal halo scalars (predicated at image edges)
    const bool hasL = (c > 0);
    const bool hasR = (c + 4 < IMG_W);
    const float l0 = hasL ? b0[rowOff - 1] : 0.f;
    const float r0 = hasR ? b0[rowOff + 4] : 0.f;
    const float l1 = hasL ? b1[rowOff - 1] : 0.f;
    const float r1 = hasR ? b1[rowOff + 4] : 0.f;

    // gx = x[min(r+1)] - x[max(r-1)]  (matches fwd/central/bwd diff)
    float g0x[4] = { dn0.x - up0.x, dn0.y - up0.y, dn0.z - up0.z, dn0.w - up0.w };
    float g1x[4] = { dn1.x - up1.x, dn1.y - up1.y, dn1.z - up1.z, dn1.w - up1.w };

    // gy = x[min(c+1)] - x[max(c-1)]
    float g0y[4], g1y[4];
    g0y[0] = cen0.y - (hasL ? l0 : cen0.x);
    g0y[1] = cen0.z - cen0.x;
    g0y[2] = cen0.w - cen0.y;
    g0y[3] = (hasR ? r0 : cen0.w) - cen0.z;
    g1y[0] = cen1.y - (hasL ? l1 : cen1.x);
    g1y[1] = cen1.z - cen1.x;
    g1y[2] = cen1.w - cen1.y;
    g1y[3] = (hasR ? r1 : cen1.w) - cen1.z;

    float s = 0.f;
#pragma unroll
    for (int i = 0; i < 4; i++) {
        const float n0  = fmaf(g0x[i], g0x[i], fmaf(g0y[i], g0y[i], EPS));
        const float n1  = fmaf(g1x[i], g1x[i], fmaf(g1y[i], g1y[i], EPS));
        const float dot = fmaf(g0x[i], g1x[i], g0y[i] * g1y[i]);
        // dot^2 / (n0*n1) == (g0/|g0| . g1/|g1|)^2
        s += __fdividef(dot * dot, n0 * n1);
    }

    // warp reduction
#pragma unroll
    for (int off = 16; off > 0; off >>= 1)
        s += __shfl_xor_sync(0xFFFFFFFFu, s, off);

    __shared__ float warp_part[8];
    const int lane = threadIdx.x & 31;
    const int wid  = threadIdx.x >> 5;
    if (lane == 0) warp_part[wid] = s;
    __syncthreads();

    if (wid == 0) {
        float bs = (lane < 8) ? warp_part[lane] : 0.f;
#pragma unroll
        for (int off = 4; off > 0; off >>= 1)
            bs += __shfl_xor_sync(0xFFFFFFFFu, bs, off);
        if (lane == 0)
            atomicAdd(&g_ngf_acc, (double)bs);
    }
}

__global__ void ngf_final_kernel(float* __restrict__ out)
{
    out[0] = (float)(1.0 - g_ngf_acc / (double)NPIX);
}

extern "C" void kernel_launch(void* const* d_in, const int* in_sizes, int n_in,
                              void* d_out, int out_size)
{
    const float* I0 = (const float*)d_in[0];
    const float* I1 = (const float*)d_in[1];
    float* out = (float*)d_out;

    ngf_zero_kernel<<<1, 1>>>();
    // 64 planes * 512 rows * 128 float4-groups = 4,194,304 threads
    ngf_main_kernel<<<NPIX / 4 / 256, 256>>>(I0, I1);
    ngf_final_kernel<<<1, 1>>>(out);
}

// round 2
// speedup vs baseline: 1.1855x; 1.1855x over previous
#include <cuda_runtime.h>

#define IMG_W 512
#define IMG_H 512
#define PLANES 64
#define PLANE_STRIDE (IMG_H * IMG_W)
#define NPIX (PLANES * PLANE_STRIDE)
#define STRIP 32
#define STRIPS (IMG_H / STRIP)          // 16
#define NBLOCKS (PLANES * STRIPS)       // 1024
#define EPS 1e-10f

// persistent scratch (statically zero-initialized; reset by last block each call)
__device__ double g_acc;
__device__ unsigned int g_count;

__global__ __launch_bounds__(128) void ngf_kernel(
    const float* __restrict__ I0, const float* __restrict__ I1,
    float* __restrict__ out)
{
    const int t     = threadIdx.x;        // 0..127, one float4 column-group each
    const int lane  = t & 31;
    const int plane = blockIdx.x >> 4;    // / STRIPS
    const int strip = blockIdx.x & (STRIPS - 1);
    const int col   = t << 2;             // 0..508

    const float* __restrict__ p0 = I0 + plane * PLANE_STRIDE + col;
    const float* __restrict__ p1 = I1 + plane * PLANE_STRIDE + col;

    const int rbase = strip * STRIP;
    const int rup   = (rbase > 0) ? rbase - 1 : 0;
    const int rdn   = (rbase + 1 < IMG_H) ? rbase + 1 : IMG_H - 1;

    // rolling rows: up = row max(r-1,0), cen = row r, dn = row min(r+1,511)
    float4 up0  = *(const float4*)(p0 + rup * IMG_W);
    float4 up1  = *(const float4*)(p1 + rup * IMG_W);
    float4 cen0 = *(const float4*)(p0 + rbase * IMG_W);
    float4 cen1 = *(const float4*)(p1 + rbase * IMG_W);
    float4 dn0  = *(const float4*)(p0 + rdn * IMG_W);
    float4 dn1  = *(const float4*)(p1 + rdn * IMG_W);

    float s = 0.f;

#pragma unroll 4
    for (int r = rbase; r < rbase + STRIP; ++r) {
        // prefetch next iteration's dn row (one iter ahead, clamped)
        int rn = r + 2;
        if (rn > IMG_H - 1) rn = IMG_H - 1;
        const float4 ndn0 = *(const float4*)(p0 + rn * IMG_W);
        const float4 ndn1 = *(const float4*)(p1 + rn * IMG_W);

        // horizontal halo: neighbor lanes' edge elements via shfl;
        // warp-edge lanes patch with an L1-hit scalar load (clamped at image edge)
        float hl0 = __shfl_up_sync(0xFFFFFFFFu, cen0.w, 1);
        float hr0 = __shfl_down_sync(0xFFFFFFFFu, cen0.x, 1);
        float hl1 = __shfl_up_sync(0xFFFFFFFFu, cen1.w, 1);
        float hr1 = __shfl_down_sync(0xFFFFFFFFu, cen1.x, 1);
        if (lane == 0) {
            hl0 = (col > 0) ? p0[r * IMG_W - 1] : cen0.x;
            hl1 = (col > 0) ? p1[r * IMG_W - 1] : cen1.x;
        }
        if (lane == 31) {
            hr0 = (col + 4 < IMG_W) ? p0[r * IMG_W + 4] : cen0.w;
            hr1 = (col + 4 < IMG_W) ? p1[r * IMG_W + 4] : cen1.w;
        }

        // gx = x[min(r+1)] - x[max(r-1)]  (fwd/central/bwd diff)
        const float g0x[4] = { dn0.x - up0.x, dn0.y - up0.y, dn0.z - up0.z, dn0.w - up0.w };
        const float g1x[4] = { dn1.x - up1.x, dn1.y - up1.y, dn1.z - up1.z, dn1.w - up1.w };
        // gy = x[min(c+1)] - x[max(c-1)]
        const float g0y[4] = { cen0.y - hl0, cen0.z - cen0.x, cen0.w - cen0.y, hr0 - cen0.z };
        const float g1y[4] = { cen1.y - hl1, cen1.z - cen1.x, cen1.w - cen1.y, hr1 - cen1.z };

#pragma unroll
        for (int i = 0; i < 4; i++) {
            const float n0  = fmaf(g0x[i], g0x[i], fmaf(g0y[i], g0y[i], EPS));
            const float n1  = fmaf(g1x[i], g1x[i], fmaf(g1y[i], g1y[i], EPS));
            const float dot = fmaf(g0x[i], g1x[i], g0y[i] * g1y[i]);
            // dot^2/(n0*n1) == (g0/|g0| . g1/|g1|)^2
            s += __fdividef(dot * dot, n0 * n1);
        }

        // rotate rows
        up0 = cen0; cen0 = dn0; dn0 = ndn0;
        up1 = cen1; cen1 = dn1; dn1 = ndn1;
    }

    // warp reduction
#pragma unroll
    for (int off = 16; off > 0; off >>= 1)
        s += __shfl_xor_sync(0xFFFFFFFFu, s, off);

    __shared__ float warp_part[4];
    const int wid = t >> 5;
    if (lane == 0) warp_part[wid] = s;
    __syncthreads();

    if (t == 0) {
        const double bs = (double)warp_part[0] + (double)warp_part[1]
                        + (double)warp_part[2] + (double)warp_part[3];
        atomicAdd(&g_acc, bs);
        __threadfence();
        const unsigned prev = atomicAdd(&g_count, 1u);
        if (prev == NBLOCKS - 1) {
            // last block: all adds visible (atomics serialize at L2)
            const double total = atomicAdd(&g_acc, 0.0);
            out[0] = (float)(1.0 - total / (double)NPIX);
            // reset for next graph replay (deterministic)
            g_acc = 0.0;
            g_count = 0u;
            __threadfence();
        }
    }
}

extern "C" void kernel_launch(void* const* d_in, const int* in_sizes, int n_in,
                              void* d_out, int out_size)
{
    const float* I0 = (const float*)d_in[0];
    const float* I1 = (const float*)d_in[1];
    float* out = (float*)d_out;

    ngf_kernel<<<NBLOCKS, 128>>>(I0, I1, out);
}

// round 3
// speedup vs baseline: 1.2705x; 1.0717x over previous
#include <cuda_runtime.h>

#define IMG_W 512
#define IMG_H 512
#define PLANES 64
#define PLANE_STRIDE (IMG_H * IMG_W)
#define NPIX (PLANES * PLANE_STRIDE)
#define STRIP 16
#define STRIPS (IMG_H / STRIP)          // 32
#define NBLOCKS (PLANES * STRIPS)       // 2048
#define EPS 1e-10f

// persistent scratch (statically zero-initialized; reset by last block each call)
__device__ double g_acc;
__device__ unsigned int g_count;

__device__ __forceinline__ float process_row(
    const float4& up0, const float4& cen0, const float4& dn0,
    const float4& up1, const float4& cen1, const float4& dn1,
    const float* __restrict__ p0, const float* __restrict__ p1,
    int r, int col, int lane)
{
    // horizontal halo: neighbor lanes' edge elements via shfl;
    // warp-edge lanes patch with a (mostly L1/L2-hit) scalar load, clamped at image edge
    float hl0 = __shfl_up_sync(0xFFFFFFFFu, cen0.w, 1);
    float hr0 = __shfl_down_sync(0xFFFFFFFFu, cen0.x, 1);
    float hl1 = __shfl_up_sync(0xFFFFFFFFu, cen1.w, 1);
    float hr1 = __shfl_down_sync(0xFFFFFFFFu, cen1.x, 1);
    if (lane == 0) {
        hl0 = (col > 0) ? p0[r * IMG_W - 1] : cen0.x;
        hl1 = (col > 0) ? p1[r * IMG_W - 1] : cen1.x;
    }
    if (lane == 31) {
        hr0 = (col + 4 < IMG_W) ? p0[r * IMG_W + 4] : cen0.w;
        hr1 = (col + 4 < IMG_W) ? p1[r * IMG_W + 4] : cen1.w;
    }

    // gx = x[min(r+1)] - x[max(r-1)]  (fwd/central/bwd diff)
    const float g0x[4] = { dn0.x - up0.x, dn0.y - up0.y, dn0.z - up0.z, dn0.w - up0.w };
    const float g1x[4] = { dn1.x - up1.x, dn1.y - up1.y, dn1.z - up1.z, dn1.w - up1.w };
    // gy = x[min(c+1)] - x[max(c-1)]
    const float g0y[4] = { cen0.y - hl0, cen0.z - cen0.x, cen0.w - cen0.y, hr0 - cen0.z };
    const float g1y[4] = { cen1.y - hl1, cen1.z - cen1.x, cen1.w - cen1.y, hr1 - cen1.z };

    float s = 0.f;
#pragma unroll
    for (int i = 0; i < 4; i++) {
        const float n0  = fmaf(g0x[i], g0x[i], fmaf(g0y[i], g0y[i], EPS));
        const float n1  = fmaf(g1x[i], g1x[i], fmaf(g1y[i], g1y[i], EPS));
        const float dot = fmaf(g0x[i], g1x[i], g0y[i] * g1y[i]);
        // dot^2/(n0*n1) == (g0/|g0| . g1/|g1|)^2
        s += __fdividef(dot * dot, n0 * n1);
    }
    return s;
}

__global__ __launch_bounds__(128) void ngf_kernel(
    const float* __restrict__ I0, const float* __restrict__ I1,
    float* __restrict__ out)
{
    const int t     = threadIdx.x;            // 0..127, one float4 column-group each
    const int lane  = t & 31;
    const int plane = blockIdx.x >> 5;        // / STRIPS
    const int strip = blockIdx.x & (STRIPS - 1);
    const int col   = t << 2;                 // 0..508

    const float* __restrict__ p0 = I0 + plane * PLANE_STRIDE + col;
    const float* __restrict__ p1 = I1 + plane * PLANE_STRIDE + col;

    const int rbase = strip * STRIP;
    const int rup   = (rbase > 0) ? rbase - 1 : 0;
    const int rdn   = (rbase + 1 < IMG_H) ? rbase + 1 : IMG_H - 1;

    // rolling rows: up = row max(r-1,0), cen = row r, dn = row min(r+1,511)
    float4 up0  = *(const float4*)(p0 + rup * IMG_W);
    float4 up1  = *(const float4*)(p1 + rup * IMG_W);
    float4 cen0 = *(const float4*)(p0 + rbase * IMG_W);
    float4 cen1 = *(const float4*)(p1 + rbase * IMG_W);
    float4 dn0  = *(const float4*)(p0 + rdn * IMG_W);
    float4 dn1  = *(const float4*)(p1 + rdn * IMG_W);

    float s = 0.f;

    // process 2 rows per iteration; prefetch both next dn-rows up front (MLP=4)
#pragma unroll 2
    for (int r = rbase; r < rbase + STRIP; r += 2) {
        int rnA = r + 2; if (rnA > IMG_H - 1) rnA = IMG_H - 1;
        int rnB = r + 3; if (rnB > IMG_H - 1) rnB = IMG_H - 1;
        const float4 nA0 = *(const float4*)(p0 + rnA * IMG_W);
        const float4 nA1 = *(const float4*)(p1 + rnA * IMG_W);
        const float4 nB0 = *(const float4*)(p0 + rnB * IMG_W);
        const float4 nB1 = *(const float4*)(p1 + rnB * IMG_W);

        s += process_row(up0, cen0, dn0, up1, cen1, dn1, p0, p1, r, col, lane);
        up0 = cen0; cen0 = dn0; dn0 = nA0;
        up1 = cen1; cen1 = dn1; dn1 = nA1;

        s += process_row(up0, cen0, dn0, up1, cen1, dn1, p0, p1, r + 1, col, lane);
        up0 = cen0; cen0 = dn0; dn0 = nB0;
        up1 = cen1; cen1 = dn1; dn1 = nB1;
    }

    // warp reduction
#pragma unroll
    for (int off = 16; off > 0; off >>= 1)
        s += __shfl_xor_sync(0xFFFFFFFFu, s, off);

    __shared__ float warp_part[4];
    const int wid = t >> 5;
    if (lane == 0) warp_part[wid] = s;
    __syncthreads();

    if (t == 0) {
        const double bs = (double)warp_part[0] + (double)warp_part[1]
                        + (double)warp_part[2] + (double)warp_part[3];
        atomicAdd(&g_acc, bs);
        __threadfence();
        const unsigned prev = atomicAdd(&g_count, 1u);
        if (prev == NBLOCKS - 1) {
            // last block: all adds visible (atomics serialize at L2)
            const double total = atomicAdd(&g_acc, 0.0);
            out[0] = (float)(1.0 - total / (double)NPIX);
            // reset for next graph replay (deterministic)
            g_acc = 0.0;
            g_count = 0u;
            __threadfence();
        }
    }
}

extern "C" void kernel_launch(void* const* d_in, const int* in_sizes, int n_in,
                              void* d_out, int out_size)
{
    const float* I0 = (const float*)d_in[0];
    const float* I1 = (const float*)d_in[1];
    float* out = (float*)d_out;

    ngf_kernel<<<NBLOCKS, 128>>>(I0, I1, out);
}